// round 1
// baseline (speedup 1.0000x reference)
#include <cuda_runtime.h>
#include <cstdint>

#define H 1024
#define W 1024
#define NB 16          // 8 pred images + 8 target images
#define TILE 32
#define SM 36          // TILE + 2*2 halo

// Scratch (allocation-free rule: __device__ globals). 3 x 64MB.
__device__ float g_A[(size_t)NB * H * W];
__device__ float g_B[(size_t)NB * H * W];
__device__ float g_skel[(size_t)NB * H * W];
__device__ float g_sums[4];

__device__ __forceinline__ float sigmoidf_(float x) {
    return 1.0f / (1.0f + __expf(-x));
}

// MODE 0: read pred/target (sigmoid on pred half), write e1 -> g_A, skel = delta
// MODE 1: read e (ab ? g_A : g_B), write e_next (other buffer), skel update
// MODE 2: like MODE 1 but skip e_next write (last step)
template <int MODE>
__global__ __launch_bounds__(1024, 2)
void step_kernel(const float* __restrict__ pred,
                 const float* __restrict__ tgt,
                 int ab)
{
    __shared__ float sA[SM * SM];  // input e_k tile
    __shared__ float sB[SM * SM];  // rowmin, later rowmax (reused)
    __shared__ float sC[SM * SM];  // eroded e_{k+1}

    const int tx = threadIdx.x, ty = threadIdx.y;
    const int tid = ty * 32 + tx;
    const int ox = blockIdx.x * TILE;
    const int oy = blockIdx.y * TILE;
    const int b  = blockIdx.z;
    const float PINF = __int_as_float(0x7f800000);
    const size_t base = (size_t)b * H * W;

    const float* e_in = (MODE == 0) ? nullptr : (ab ? g_A : g_B);
    float*       e_out = (MODE == 0) ? g_A     : (ab ? g_B : g_A);

    // ---- load 36x36 input tile (erode pad = +inf) ----
    #pragma unroll
    for (int i = tid; i < SM * SM; i += 1024) {
        int ly = i / SM, lx = i % SM;
        int gy = oy + ly - 2, gx = ox + lx - 2;
        float v = PINF;
        if ((unsigned)gy < H && (unsigned)gx < W) {
            if (MODE == 0) {
                if (b < 8) v = sigmoidf_(pred[((size_t)b * H + gy) * W + gx]);
                else       v = tgt[((size_t)(b - 8) * H + gy) * W + gx];
            } else {
                v = e_in[base + (size_t)gy * W + gx];
            }
        }
        sA[i] = v;
    }
    __syncthreads();

    // ---- rowmin: lx in [1,34], all 36 rows ----
    #pragma unroll
    for (int i = tid; i < SM * 34; i += 1024) {
        int ly = i / 34, lx = i % 34 + 1;
        const float* r = &sA[ly * SM + lx];
        sB[ly * SM + lx] = fminf(fminf(r[-1], r[0]), r[1]);
    }
    __syncthreads();

    // ---- colmin -> eroded e_{k+1} on [1,34]^2; OOB positions -> -inf (dilate pad) ----
    #pragma unroll
    for (int i = tid; i < 34 * 34; i += 1024) {
        int ly = i / 34 + 1, lx = i % 34 + 1;
        int gy = oy + ly - 2, gx = ox + lx - 2;
        float v;
        if ((unsigned)gy < H && (unsigned)gx < W)
            v = fminf(fminf(sB[(ly - 1) * SM + lx], sB[ly * SM + lx]), sB[(ly + 1) * SM + lx]);
        else
            v = -PINF;
        sC[ly * SM + lx] = v;
    }
    __syncthreads();

    // ---- write e_{k+1} center ----
    if (MODE != 2) {
        e_out[base + (size_t)(oy + ty) * W + ox + tx] = sC[(ty + 2) * SM + tx + 2];
    }

    // ---- rowmax of eroded: lx in [2,33], ly in [1,34] ----
    #pragma unroll
    for (int i = tid; i < 34 * TILE; i += 1024) {
        int ly = i / TILE + 1, lx = i % TILE + 2;
        const float* r = &sC[ly * SM + lx];
        sB[ly * SM + lx] = fmaxf(fmaxf(r[-1], r[0]), r[1]);
    }
    __syncthreads();

    // ---- colmax -> open, delta, skel update ----
    {
        int ly = ty + 2, lx = tx + 2;
        float open_v = fmaxf(fmaxf(sB[(ly - 1) * SM + lx], sB[ly * SM + lx]),
                             sB[(ly + 1) * SM + lx]);
        float e = sA[ly * SM + lx];
        float delta = fmaxf(e - open_v, 0.0f);
        size_t idx = base + (size_t)(oy + ty) * W + ox + tx;
        if (MODE == 0) {
            g_skel[idx] = delta;
        } else {
            float s = g_skel[idx];
            g_skel[idx] = s + fmaxf(delta - s * delta, 0.0f);
        }
    }
}

__global__ void zero_sums_kernel() {
    if (threadIdx.x < 4) g_sums[threadIdx.x] = 0.0f;
}

__global__ __launch_bounds__(256)
void reduce_kernel(const float* __restrict__ pred, const float* __restrict__ tgt) {
    const size_t N4 = (size_t)8 * H * W / 4;  // float4 count per half
    float s1 = 0.f, s2 = 0.f, s3 = 0.f, s4 = 0.f;
    size_t stride = (size_t)gridDim.x * blockDim.x;
    const float4* skp = (const float4*)g_skel;             // skel(pred) half
    const float4* skt = (const float4*)g_skel + N4;        // skel(target) half
    const float4* tp  = (const float4*)tgt;
    const float4* pp  = (const float4*)pred;
    for (size_t i = (size_t)blockIdx.x * blockDim.x + threadIdx.x; i < N4; i += stride) {
        float4 sp = skp[i];
        float4 t  = tp[i];
        float4 st = skt[i];
        float4 p  = pp[i];
        s1 += sp.x * t.x + sp.y * t.y + sp.z * t.z + sp.w * t.w;
        s2 += sp.x + sp.y + sp.z + sp.w;
        s3 += st.x * sigmoidf_(p.x) + st.y * sigmoidf_(p.y)
            + st.z * sigmoidf_(p.z) + st.w * sigmoidf_(p.w);
        s4 += st.x + st.y + st.z + st.w;
    }
    // warp reduce
    #pragma unroll
    for (int off = 16; off; off >>= 1) {
        s1 += __shfl_down_sync(0xffffffffu, s1, off);
        s2 += __shfl_down_sync(0xffffffffu, s2, off);
        s3 += __shfl_down_sync(0xffffffffu, s3, off);
        s4 += __shfl_down_sync(0xffffffffu, s4, off);
    }
    __shared__ float sh[4][8];
    int lane = threadIdx.x & 31, w = threadIdx.x >> 5;
    if (lane == 0) { sh[0][w] = s1; sh[1][w] = s2; sh[2][w] = s3; sh[3][w] = s4; }
    __syncthreads();
    if (threadIdx.x < 8) {
        float a1 = sh[0][threadIdx.x], a2 = sh[1][threadIdx.x];
        float a3 = sh[2][threadIdx.x], a4 = sh[3][threadIdx.x];
        #pragma unroll
        for (int off = 4; off; off >>= 1) {
            a1 += __shfl_down_sync(0xffu, a1, off);
            a2 += __shfl_down_sync(0xffu, a2, off);
            a3 += __shfl_down_sync(0xffu, a3, off);
            a4 += __shfl_down_sync(0xffu, a4, off);
        }
        if (threadIdx.x == 0) {
            atomicAdd(&g_sums[0], a1);
            atomicAdd(&g_sums[1], a2);
            atomicAdd(&g_sums[2], a3);
            atomicAdd(&g_sums[3], a4);
        }
    }
}

__global__ void final_kernel(float* __restrict__ out) {
    float S1 = g_sums[0], S2 = g_sums[1], S3 = g_sums[2], S4 = g_sums[3];
    float tp = (S1 + 1.0f) / (S2 + 1.0f);
    float ts = (S3 + 1.0f) / (S4 + 1.0f);
    float cl = 2.0f * tp * ts / (tp + ts + 1e-7f);
    out[0] = 1.0f - cl;
}

extern "C" void kernel_launch(void* const* d_in, const int* in_sizes, int n_in,
                              void* d_out, int out_size)
{
    const float* pred = (const float*)d_in[0];
    const float* tgt  = (const float*)d_in[1];
    float* out = (float*)d_out;

    dim3 blk(32, 32);
    dim3 grd(W / TILE, H / TILE, NB);

    zero_sums_kernel<<<1, 32>>>();

    // step 0: e1 = erode(img) -> g_A ; skel = relu(img - dilate(e1))
    step_kernel<0><<<grd, blk>>>(pred, tgt, 0);

    // steps k = 1..10: e in (ab ? g_A : g_B) -> other buffer
    // k=1 reads g_A (ab=1), k=2 reads g_B (ab=0), ...
    for (int k = 1; k <= 10; k++) {
        int ab = (k & 1);  // odd k reads g_A
        if (k < 10) step_kernel<1><<<grd, blk>>>(pred, tgt, ab);
        else        step_kernel<2><<<grd, blk>>>(pred, tgt, ab);
    }

    reduce_kernel<<<2048, 256>>>(pred, tgt);
    final_kernel<<<1, 1>>>(out);
    (void)in_sizes; (void)n_in; (void)out_size;
}

// round 2
// speedup vs baseline: 2.6031x; 2.6031x over previous
#include <cuda_runtime.h>
#include <cstdint>

#define H 1024
#define W 1024
#define TX 104          // output tile width (floats)
#define TY 32           // output tile height
#define BF4 32          // buffer width in float4 (128 floats)
#define BH 56           // buffer height = TY + 2*HALO
#define HALO 12         // 11 steps -> halo 12
#define GX 10           // ceil(1024/104)
#define GY 32
#define NB 16           // 8 pred + 8 target images

__device__ float g_sums[4];

__device__ __forceinline__ float sig_(float x) { return 1.0f / (1.0f + __expf(-x)); }

// erode min with pad-remap: pads stored as -1.0, |{-1}| = 1.0 >= all real values in [0,1]
__device__ __forceinline__ float min3a(float a, float b, float c) {
    return fminf(fabsf(a), fminf(fabsf(b), fabsf(c)));
}
__device__ __forceinline__ float max3_(float a, float b, float c) {
    return fmaxf(a, fmaxf(b, c));
}

__global__ __launch_bounds__(1024, 2)
void cl_main(const float* __restrict__ pred, const float* __restrict__ tgt)
{
    extern __shared__ float4 sbuf[];
    float4* E = sbuf;                 // e_k
    float4* R = sbuf + BH * BF4;      // row-pass temp (rowmin / rowmax)
    float4* N = sbuf + 2 * BH * BF4;  // e_{k+1}

    const int tx = threadIdx.x;       // f4 column 0..31
    const int ty = threadIdx.y;       // 0..31
    const int bx = blockIdx.x, by = blockIdx.y, b = blockIdx.z;
    const int ox = bx * TX, oy = by * TY;
    const int x0 = ox - HALO, y0 = oy - HALO;
    const bool isPred = (b < 8);
    const float* img = isPred ? pred + (size_t)b * H * W
                              : tgt + (size_t)(b - 8) * H * W;
    const bool bord = (bx == 0) | (bx == GX - 1) | (by == 0) | (by == GY - 1);
    const int gxv = x0 + 4 * tx;      // global x of this thread's f4 .x component

    // ---- load tile; image-OOB cells get pad -1.0 ----
    for (int r = ty; r < BH; r += 32) {
        int gy = y0 + r;
        float4 v;
        if ((unsigned)gy < H && gxv >= 0 && gxv + 3 < W) {
            v = *reinterpret_cast<const float4*>(&img[(size_t)gy * W + gxv]);
            if (isPred) { v.x = sig_(v.x); v.y = sig_(v.y); v.z = sig_(v.z); v.w = sig_(v.w); }
        } else if ((unsigned)gy < H) {
            const float* row = &img[(size_t)gy * W];
            v.x = ((unsigned)(gxv + 0) < W) ? (isPred ? sig_(row[gxv + 0]) : row[gxv + 0]) : -1.0f;
            v.y = ((unsigned)(gxv + 1) < W) ? (isPred ? sig_(row[gxv + 1]) : row[gxv + 1]) : -1.0f;
            v.z = ((unsigned)(gxv + 2) < W) ? (isPred ? sig_(row[gxv + 2]) : row[gxv + 2]) : -1.0f;
            v.w = ((unsigned)(gxv + 3) < W) ? (isPred ? sig_(row[gxv + 3]) : row[gxv + 3]) : -1.0f;
        } else {
            v = make_float4(-1.0f, -1.0f, -1.0f, -1.0f);
        }
        E[r * BF4 + tx] = v;
    }
    __syncthreads();

    float4 skl = make_float4(0.f, 0.f, 0.f, 0.f);

    #pragma unroll 1
    for (int k = 0; k < 11; k++) {
        const int clo = (k + 1) >> 2;        // needed f4-col range shrinks with k
        const int chi = (126 - k) >> 2;

        // ---- rowmin (erode horizontal): E -> R, rows [k, 55-k] ----
        if (tx >= clo && tx <= chi) {
            const int txl = (tx == 0) ? 0 : tx - 1;
            const int txr = (tx == 31) ? 31 : tx + 1;
            for (int r = k + ty; r <= BH - 1 - k; r += 32) {
                float4 c  = E[r * BF4 + tx];
                float4 l  = E[r * BF4 + txl];
                float4 rr = E[r * BF4 + txr];
                float4 o;
                o.x = min3a(l.w, c.x, c.y);
                o.y = min3a(c.x, c.y, c.z);
                o.z = min3a(c.y, c.z, c.w);
                o.w = min3a(c.z, c.w, rr.x);
                R[r * BF4 + tx] = o;
            }
        }
        __syncthreads();

        // ---- colmin (erode vertical): R -> N, rows [k+1, 54-k]; force OOB = -1 ----
        if (tx >= clo && tx <= chi) {
            for (int r = k + 1 + ty; r <= 54 - k; r += 32) {
                float4 a = R[(r - 1) * BF4 + tx];
                float4 m = R[r * BF4 + tx];
                float4 d = R[(r + 1) * BF4 + tx];
                float4 o;
                o.x = fminf(a.x, fminf(m.x, d.x));
                o.y = fminf(a.y, fminf(m.y, d.y));
                o.z = fminf(a.z, fminf(m.z, d.z));
                o.w = fminf(a.w, fminf(m.w, d.w));
                if (bord) {
                    int gy = y0 + r;
                    bool ry = (unsigned)gy >= H;
                    if (ry || (unsigned)(gxv + 0) >= W) o.x = -1.0f;
                    if (ry || (unsigned)(gxv + 1) >= W) o.y = -1.0f;
                    if (ry || (unsigned)(gxv + 2) >= W) o.z = -1.0f;
                    if (ry || (unsigned)(gxv + 3) >= W) o.w = -1.0f;
                }
                N[r * BF4 + tx] = o;
            }
        }
        __syncthreads();

        // ---- rowmax (dilate horizontal): N -> R, rows [11,44], f4 cols [3,28] ----
        if (tx >= 3 && tx <= 28) {
            for (int r = 11 + ty; r <= 44; r += 32) {
                float4 c  = N[r * BF4 + tx];
                float4 l  = N[r * BF4 + tx - 1];
                float4 rr = N[r * BF4 + tx + 1];
                float4 o;
                o.x = max3_(l.w, c.x, c.y);
                o.y = max3_(c.x, c.y, c.z);
                o.z = max3_(c.y, c.z, c.w);
                o.w = max3_(c.z, c.w, rr.x);
                R[r * BF4 + tx] = o;
            }
        }
        __syncthreads();

        // ---- colmax (dilate vertical) -> open; delta; skel update (center only) ----
        if (tx < 26) {
            const int r = 12 + ty, cc = 3 + tx;
            float4 a = R[(r - 1) * BF4 + cc];
            float4 m = R[r * BF4 + cc];
            float4 d = R[(r + 1) * BF4 + cc];
            float4 e = E[r * BF4 + cc];
            float opx = max3_(a.x, m.x, d.x);
            float opy = max3_(a.y, m.y, d.y);
            float opz = max3_(a.z, m.z, d.z);
            float opw = max3_(a.w, m.w, d.w);
            float dx = fmaxf(e.x - opx, 0.0f);
            float dy = fmaxf(e.y - opy, 0.0f);
            float dz = fmaxf(e.z - opz, 0.0f);
            float dw = fmaxf(e.w - opw, 0.0f);
            if (k == 0) {
                skl = make_float4(dx, dy, dz, dw);
            } else {
                skl.x += fmaxf(dx - skl.x * dx, 0.0f);
                skl.y += fmaxf(dy - skl.y * dy, 0.0f);
                skl.z += fmaxf(dz - skl.z * dz, 0.0f);
                skl.w += fmaxf(dw - skl.w * dw, 0.0f);
            }
        }
        __syncthreads();

        // ping-pong e buffers
        float4* t = E; E = N; N = t;
    }

    // ---- per-thread partial sums (skel*other, skel) ----
    float sa = 0.f, sb = 0.f;
    if (tx < 26) {
        const int gy = oy + ty;
        const int gx = ox + 4 * tx;
        const float* other = isPred ? (tgt + (size_t)b * H * W)
                                    : (pred + (size_t)(b - 8) * H * W);
        const float* row = &other[(size_t)gy * W];
        if (gx + 3 < W) {
            float4 w = *reinterpret_cast<const float4*>(&row[gx]);
            if (!isPred) { w.x = sig_(w.x); w.y = sig_(w.y); w.z = sig_(w.z); w.w = sig_(w.w); }
            sa = skl.x * w.x + skl.y * w.y + skl.z * w.z + skl.w * w.w;
            sb = skl.x + skl.y + skl.z + skl.w;
        } else {
            float s[4] = { skl.x, skl.y, skl.z, skl.w };
            #pragma unroll
            for (int i = 0; i < 4; i++) {
                if ((unsigned)(gx + i) < W) {
                    float w = row[gx + i];
                    if (!isPred) w = sig_(w);
                    sa += s[i] * w;
                    sb += s[i];
                }
            }
        }
    }

    // ---- block reduction -> atomics ----
    #pragma unroll
    for (int o = 16; o; o >>= 1) {
        sa += __shfl_down_sync(0xffffffffu, sa, o);
        sb += __shfl_down_sync(0xffffffffu, sb, o);
    }
    float* red = (float*)sbuf;
    if (tx == 0) { red[ty] = sa; red[32 + ty] = sb; }
    __syncthreads();
    if (ty == 0) {
        float a = red[tx], c = red[32 + tx];
        #pragma unroll
        for (int o = 16; o; o >>= 1) {
            a += __shfl_down_sync(0xffffffffu, a, o);
            c += __shfl_down_sync(0xffffffffu, c, o);
        }
        if (tx == 0) {
            atomicAdd(&g_sums[isPred ? 0 : 2], a);
            atomicAdd(&g_sums[isPred ? 1 : 3], c);
        }
    }
}

__global__ void zero_sums_kernel() {
    if (threadIdx.x < 4) g_sums[threadIdx.x] = 0.0f;
}

__global__ void final_kernel(float* __restrict__ out) {
    float S1 = g_sums[0], S2 = g_sums[1], S3 = g_sums[2], S4 = g_sums[3];
    float tp = (S1 + 1.0f) / (S2 + 1.0f);
    float ts = (S3 + 1.0f) / (S4 + 1.0f);
    float cl = 2.0f * tp * ts / (tp + ts + 1e-7f);
    out[0] = 1.0f - cl;
}

extern "C" void kernel_launch(void* const* d_in, const int* in_sizes, int n_in,
                              void* d_out, int out_size)
{
    const float* pred = (const float*)d_in[0];
    const float* tgt  = (const float*)d_in[1];
    float* out = (float*)d_out;

    size_t shmem = (size_t)3 * BH * BF4 * sizeof(float4);  // 86016 bytes
    cudaFuncSetAttribute(cl_main, cudaFuncAttributeMaxDynamicSharedMemorySize, (int)shmem);

    zero_sums_kernel<<<1, 32>>>();
    cl_main<<<dim3(GX, GY, NB), dim3(32, 32), shmem>>>(pred, tgt);
    final_kernel<<<1, 1>>>(out);

    (void)in_sizes; (void)n_in; (void)out_size;
}

// round 3
// speedup vs baseline: 6.8382x; 2.6269x over previous
#include <cuda_runtime.h>
#include <cstdint>

#define H 1024
#define W 1024
#define OTX 104         // output tile width (floats)
#define OTY 40          // output tile height
#define GX 10           // 10*104 = 1040 >= 1024
#define GYB 26          // 26*40  = 1040 >= 1024
#define NB 16           // 8 pred + 8 target
#define BROWS 64        // buffer rows = OTY + 2*12

__device__ float g_sums[4];

__device__ __forceinline__ float sig_(float x) { return 1.0f / (1.0f + __expf(-x)); }

__device__ __forceinline__ float4 vmin4(float4 a, float4 b) {
    return make_float4(fminf(a.x,b.x), fminf(a.y,b.y), fminf(a.z,b.z), fminf(a.w,b.w));
}
__device__ __forceinline__ float4 vmax4(float4 a, float4 b) {
    return make_float4(fmaxf(a.x,b.x), fmaxf(a.y,b.y), fmaxf(a.z,b.z), fmaxf(a.w,b.w));
}

// horizontal 3-min with |.| pad-remap (pads stored as -1; |-1| = 1 >= all data in [0,1))
__device__ __forceinline__ float4 hmin_abs(float4 v) {
    float lw = __shfl_up_sync(0xffffffffu, v.w, 1);    // lane0: own value (buffer-edge garbage OK)
    float rx = __shfl_down_sync(0xffffffffu, v.x, 1);  // lane31: own value
    float ax = fabsf(v.x), ay = fabsf(v.y), az = fabsf(v.z), aw = fabsf(v.w);
    float t1 = fminf(ax, ay), t2 = fminf(ay, az), t3 = fminf(az, aw);
    float4 o;
    o.x = fminf(fabsf(lw), t1);
    o.y = fminf(t1, az);
    o.z = fminf(t2, aw);
    o.w = fminf(t3, fabsf(rx));
    return o;
}

__device__ __forceinline__ float4 hmax_(float4 v) {
    float lw = __shfl_up_sync(0xffffffffu, v.w, 1);
    float rx = __shfl_down_sync(0xffffffffu, v.x, 1);
    float t1 = fmaxf(v.x, v.y), t2 = fmaxf(v.y, v.z), t3 = fmaxf(v.z, v.w);
    float4 o;
    o.x = fmaxf(lw, t1);
    o.y = fmaxf(t1, v.z);
    o.z = fmaxf(t2, v.w);
    o.w = fmaxf(t3, rx);
    return o;
}

__device__ __forceinline__ float4 load_row(const float* __restrict__ img, int gy, int gx0, bool doSig)
{
    float4 v;
    if ((unsigned)gy < H) {
        const float* row = img + (size_t)gy * W;
        if (gx0 >= 0 && gx0 + 3 < W) {
            v = *reinterpret_cast<const float4*>(row + gx0);
            if (doSig) { v.x = sig_(v.x); v.y = sig_(v.y); v.z = sig_(v.z); v.w = sig_(v.w); }
        } else {
            v.x = ((unsigned)(gx0+0) < W) ? (doSig ? sig_(row[gx0+0]) : row[gx0+0]) : -1.0f;
            v.y = ((unsigned)(gx0+1) < W) ? (doSig ? sig_(row[gx0+1]) : row[gx0+1]) : -1.0f;
            v.z = ((unsigned)(gx0+2) < W) ? (doSig ? sig_(row[gx0+2]) : row[gx0+2]) : -1.0f;
            v.w = ((unsigned)(gx0+3) < W) ? (doSig ? sig_(row[gx0+3]) : row[gx0+3]) : -1.0f;
        }
    } else {
        v = make_float4(-1.f, -1.f, -1.f, -1.f);
    }
    return v;
}

__global__ __launch_bounds__(1024, 1)
void cl_main(const float* __restrict__ pred, const float* __restrict__ tgt)
{
    extern __shared__ float4 smem_[];
    float4 (*exA)[32] = (float4(*)[32])smem_;                 // erode vertical exchange
    float4 (*exB)[32] = (float4(*)[32])(smem_ + BROWS * 32);  // dilate vertical exchange

    const int tid  = threadIdx.x;
    const int lane = tid & 31;
    const int wid  = tid >> 5;
    const int r0   = wid * 2;
    const int bx = blockIdx.x, by = blockIdx.y, b = blockIdx.z;
    const bool isPred = (b < 8);
    const float* img = isPred ? pred + (size_t)b * H * W
                              : tgt  + (size_t)(b - 8) * H * W;

    const int gx0 = bx * OTX - 12 + 4 * lane;  // global col of component .x
    const int gy0 = by * OTY - 12 + r0;        // global row of this thread's row 0
    const bool bord = (bx == 0) | (bx == GX - 1) | (by == 0) | (by == GYB - 1);

    // image-validity masks for this thread's cells (constant across steps)
    const bool kr0 = (unsigned)gy0     < H;
    const bool kr1 = (unsigned)(gy0+1) < H;
    const bool kc0 = (unsigned)(gx0+0) < W;
    const bool kc1 = (unsigned)(gx0+1) < W;
    const bool kc2 = (unsigned)(gx0+2) < W;
    const bool kc3 = (unsigned)(gx0+3) < W;

    // ---- load e_0 (2 rows per thread), pads = -1 ----
    float4 e0 = load_row(img, gy0,     gx0, isPred);
    float4 e1 = load_row(img, gy0 + 1, gx0, isPred);

    float4 sk0 = make_float4(0.f, 0.f, 0.f, 0.f);
    float4 sk1 = sk0;

    const int upR = (wid == 0)  ? 0        : r0 - 1;
    const int dnR = (wid == 31) ? BROWS-1  : r0 + 2;
    const bool dilateW = (wid >= 5) && (wid <= 26);
    const bool centerW = (wid >= 6) && (wid <= 25) && (lane >= 3) && (lane <= 28);

    #pragma unroll
    for (int k = 0; k < 11; k++) {
        // ---- erode: horizontal min (regs+shuffle), vertical via 2-row exchange ----
        float4 rm0 = hmin_abs(e0);
        float4 rm1 = hmin_abs(e1);
        exA[r0][lane]     = rm0;
        exA[r0 + 1][lane] = rm1;
        __syncthreads();
        float4 up = exA[upR][lane];
        float4 dn = exA[dnR][lane];
        float4 t  = vmin4(rm0, rm1);
        float4 en0 = vmin4(up, t);
        float4 en1 = vmin4(t, dn);

        // force image-OOB cells back to pad (-1); only border blocks
        if (bord) {
            en0.x = (kr0 & kc0) ? en0.x : -1.f;
            en0.y = (kr0 & kc1) ? en0.y : -1.f;
            en0.z = (kr0 & kc2) ? en0.z : -1.f;
            en0.w = (kr0 & kc3) ? en0.w : -1.f;
            en1.x = (kr1 & kc0) ? en1.x : -1.f;
            en1.y = (kr1 & kc1) ? en1.y : -1.f;
            en1.z = (kr1 & kc2) ? en1.z : -1.f;
            en1.w = (kr1 & kc3) ? en1.w : -1.f;
        }

        // ---- dilate (only warps near center), delta + skel update ----
        if (dilateW) {
            float4 xm0 = hmax_(en0);
            float4 xm1 = hmax_(en1);
            exB[r0][lane]     = xm0;
            exB[r0 + 1][lane] = xm1;
        }
        __syncthreads();
        if (centerW) {
            float4 u  = exB[r0 - 1][lane];
            float4 m0 = exB[r0][lane];
            float4 m1 = exB[r0 + 1][lane];
            float4 d  = exB[r0 + 2][lane];
            float4 tt  = vmax4(m0, m1);
            float4 op0 = vmax4(u, tt);
            float4 op1 = vmax4(tt, d);
            // delta = relu(e - open); skel += relu(delta - skel*delta)
            float d0x = fmaxf(e0.x - op0.x, 0.f), d0y = fmaxf(e0.y - op0.y, 0.f);
            float d0z = fmaxf(e0.z - op0.z, 0.f), d0w = fmaxf(e0.w - op0.w, 0.f);
            float d1x = fmaxf(e1.x - op1.x, 0.f), d1y = fmaxf(e1.y - op1.y, 0.f);
            float d1z = fmaxf(e1.z - op1.z, 0.f), d1w = fmaxf(e1.w - op1.w, 0.f);
            sk0.x += fmaxf(fmaf(-sk0.x, d0x, d0x), 0.f);
            sk0.y += fmaxf(fmaf(-sk0.y, d0y, d0y), 0.f);
            sk0.z += fmaxf(fmaf(-sk0.z, d0z, d0z), 0.f);
            sk0.w += fmaxf(fmaf(-sk0.w, d0w, d0w), 0.f);
            sk1.x += fmaxf(fmaf(-sk1.x, d1x, d1x), 0.f);
            sk1.y += fmaxf(fmaf(-sk1.y, d1y, d1y), 0.f);
            sk1.z += fmaxf(fmaf(-sk1.z, d1z, d1z), 0.f);
            sk1.w += fmaxf(fmaf(-sk1.w, d1w, d1w), 0.f);
        }
        e0 = en0; e1 = en1;
    }

    // ---- partial sums: sa = sum(skel * other'), sb = sum(skel), masked to image ----
    float sa = 0.f, sb = 0.f;
    if (centerW) {
        const float* oimg = isPred ? tgt  + (size_t)b * H * W
                                   : pred + (size_t)(b - 8) * H * W;
        const bool oSig = !isPred;
        #pragma unroll
        for (int r = 0; r < 2; r++) {
            int gy = gy0 + r;
            if ((unsigned)gy < H) {
                float4 sk = (r == 0) ? sk0 : sk1;
                const float* row = oimg + (size_t)gy * W;
                if (kc0 & kc3) {
                    float4 w = *reinterpret_cast<const float4*>(row + gx0);
                    if (oSig) { w.x = sig_(w.x); w.y = sig_(w.y); w.z = sig_(w.z); w.w = sig_(w.w); }
                    sa += sk.x * w.x + sk.y * w.y + sk.z * w.z + sk.w * w.w;
                    sb += sk.x + sk.y + sk.z + sk.w;
                } else {
                    float s[4] = { sk.x, sk.y, sk.z, sk.w };
                    bool kk[4] = { kc0, kc1, kc2, kc3 };
                    #pragma unroll
                    for (int i = 0; i < 4; i++) {
                        if (kk[i]) {
                            float w = row[gx0 + i];
                            if (oSig) w = sig_(w);
                            sa += s[i] * w;
                            sb += s[i];
                        }
                    }
                }
            }
        }
    }

    // ---- block reduction (reuse exA as scratch) ----
    #pragma unroll
    for (int o = 16; o; o >>= 1) {
        sa += __shfl_down_sync(0xffffffffu, sa, o);
        sb += __shfl_down_sync(0xffffffffu, sb, o);
    }
    __syncthreads();                      // exA last read was LDS in final step
    float2* sred = (float2*)exA;
    if (lane == 0) sred[wid] = make_float2(sa, sb);
    __syncthreads();
    if (wid == 0) {
        float2 p = sred[lane];
        float a = p.x, c = p.y;
        #pragma unroll
        for (int o = 16; o; o >>= 1) {
            a += __shfl_down_sync(0xffffffffu, a, o);
            c += __shfl_down_sync(0xffffffffu, c, o);
        }
        if (lane == 0) {
            atomicAdd(&g_sums[isPred ? 0 : 2], a);
            atomicAdd(&g_sums[isPred ? 1 : 3], c);
        }
    }
}

__global__ void zero_sums_kernel() {
    if (threadIdx.x < 4) g_sums[threadIdx.x] = 0.0f;
}

__global__ void final_kernel(float* __restrict__ out) {
    float S1 = g_sums[0], S2 = g_sums[1], S3 = g_sums[2], S4 = g_sums[3];
    float tp = (S1 + 1.0f) / (S2 + 1.0f);
    float ts = (S3 + 1.0f) / (S4 + 1.0f);
    float cl = 2.0f * tp * ts / (tp + ts + 1e-7f);
    out[0] = 1.0f - cl;
}

extern "C" void kernel_launch(void* const* d_in, const int* in_sizes, int n_in,
                              void* d_out, int out_size)
{
    const float* pred = (const float*)d_in[0];
    const float* tgt  = (const float*)d_in[1];
    float* out = (float*)d_out;

    size_t shmem = (size_t)2 * BROWS * 32 * sizeof(float4);  // 65536 bytes
    cudaFuncSetAttribute(cl_main, cudaFuncAttributeMaxDynamicSharedMemorySize, (int)shmem);

    zero_sums_kernel<<<1, 32>>>();
    cl_main<<<dim3(GX, GYB, NB), 1024, shmem>>>(pred, tgt);
    final_kernel<<<1, 1>>>(out);

    (void)in_sizes; (void)n_in; (void)out_size;
}

// round 4
// speedup vs baseline: 7.9387x; 1.1609x over previous
#include <cuda_runtime.h>
#include <cstdint>

#define H 1024
#define W 1024
#define TS 104          // square output tile (floats)
#define G  10           // 10*104 = 1040 >= 1024 (both dims)
#define NB 16           // 8 pred + 8 target

__device__ float g_sums[4];

__device__ __forceinline__ float sig_(float x) { return 1.0f / (1.0f + __expf(-x)); }

__device__ __forceinline__ float4 vmin3(float4 a, float4 b, float4 c) {
    return make_float4(fminf(a.x, fminf(b.x, c.x)), fminf(a.y, fminf(b.y, c.y)),
                       fminf(a.z, fminf(b.z, c.z)), fminf(a.w, fminf(b.w, c.w)));
}
__device__ __forceinline__ float4 vmax3(float4 a, float4 b, float4 c) {
    return make_float4(fmaxf(a.x, fmaxf(b.x, c.x)), fmaxf(a.y, fmaxf(b.y, c.y)),
                       fmaxf(a.z, fmaxf(b.z, c.z)), fmaxf(a.w, fmaxf(b.w, c.w)));
}

// horizontal 3-min with |.| pad-remap (pads stored as -1; |-1|=1 >= all data in [0,1))
__device__ __forceinline__ float4 hmin_abs(float4 v) {
    float lw = __shfl_up_sync(0xffffffffu, v.w, 1);
    float rx = __shfl_down_sync(0xffffffffu, v.x, 1);
    float ax = fabsf(v.x), ay = fabsf(v.y), az = fabsf(v.z), aw = fabsf(v.w);
    float t1 = fminf(ax, ay), t2 = fminf(ay, az), t3 = fminf(az, aw);
    float4 o;
    o.x = fminf(fabsf(lw), t1);
    o.y = fminf(t1, az);
    o.z = fminf(t2, aw);
    o.w = fminf(t3, fabsf(rx));
    return o;
}

__device__ __forceinline__ float4 hmax_(float4 v) {
    float lw = __shfl_up_sync(0xffffffffu, v.w, 1);
    float rx = __shfl_down_sync(0xffffffffu, v.x, 1);
    float t1 = fmaxf(v.x, v.y), t2 = fmaxf(v.y, v.z), t3 = fmaxf(v.z, v.w);
    float4 o;
    o.x = fmaxf(lw, t1);
    o.y = fmaxf(t1, v.z);
    o.z = fmaxf(t2, v.w);
    o.w = fmaxf(t3, rx);
    return o;
}

__device__ __forceinline__ float4 load_row(const float* __restrict__ img, int gy, int gx0, bool doSig)
{
    float4 v;
    if ((unsigned)gy < H) {
        const float* row = img + (size_t)gy * W;
        if (gx0 >= 0 && gx0 + 3 < W) {
            v = *reinterpret_cast<const float4*>(row + gx0);
            if (doSig) { v.x = sig_(v.x); v.y = sig_(v.y); v.z = sig_(v.z); v.w = sig_(v.w); }
        } else {
            v.x = ((unsigned)(gx0+0) < W) ? (doSig ? sig_(row[gx0+0]) : row[gx0+0]) : -1.0f;
            v.y = ((unsigned)(gx0+1) < W) ? (doSig ? sig_(row[gx0+1]) : row[gx0+1]) : -1.0f;
            v.z = ((unsigned)(gx0+2) < W) ? (doSig ? sig_(row[gx0+2]) : row[gx0+2]) : -1.0f;
            v.w = ((unsigned)(gx0+3) < W) ? (doSig ? sig_(row[gx0+3]) : row[gx0+3]) : -1.0f;
        }
    } else {
        v = make_float4(-1.f, -1.f, -1.f, -1.f);
    }
    return v;
}

// buffer: 128 rows x 128 cols; warp w owns rows 4w..4w+3; lane = f4 column.
// exchange: only boundary rows cross warps (rows 0 and 3 of each warp).
__global__ __launch_bounds__(1024, 1)
void cl_main(const float* __restrict__ pred, const float* __restrict__ tgt)
{
    extern __shared__ float4 smem_[];
    float4* exA = smem_;           // [wid*2 + s][lane] : erode rowmin boundary rows
    float4* exB = smem_ + 2048;    // [wid*2 + s][lane] : dilate rowmax boundary rows

    const int tid  = threadIdx.x;
    const int lane = tid & 31;
    const int wid  = tid >> 5;
    const int bx = blockIdx.x, by = blockIdx.y, b = blockIdx.z;
    const bool isPred = (b < 8);
    const float* img = isPred ? pred + (size_t)b * H * W
                              : tgt  + (size_t)(b - 8) * H * W;

    const int gx0 = bx * TS - 12 + 4 * lane;     // global col of component .x
    const int gy0 = by * TS - 12 + 4 * wid;      // global row of this thread's row 0
    const bool bord = (bx == 0) | (bx == G - 1) | (by == 0) | (by == G - 1);

    // ---- load e (4 rows), pads = -1 ----
    float4 e[4];
    #pragma unroll
    for (int i = 0; i < 4; i++) e[i] = load_row(img, gy0 + i, gx0, isPred);

    float4 sk[4];
    #pragma unroll
    for (int i = 0; i < 4; i++) sk[i] = make_float4(0.f, 0.f, 0.f, 0.f);

    const int upIdx = (wid == 0)  ? 1            : (wid - 1) * 2 + 1;  // neighbor rm3 (self garbage ok)
    const int dnIdx = (wid == 31) ? wid * 2      : (wid + 1) * 2;      // neighbor rm0
    const bool dilateW = (wid >= 2) && (wid <= 29);
    const bool centerW = (wid >= 3) && (wid <= 28) && (lane >= 3) && (lane <= 28);

    #pragma unroll 1
    for (int k = 0; k < 11; k++) {
        // ---- erode horizontal (regs + shuffle) ----
        float4 rm[4];
        #pragma unroll
        for (int i = 0; i < 4; i++) rm[i] = hmin_abs(e[i]);

        exA[(wid * 2 + 0) * 32 + lane] = rm[0];
        exA[(wid * 2 + 1) * 32 + lane] = rm[3];
        __syncthreads();
        float4 up = exA[upIdx * 32 + lane];
        float4 dn = exA[dnIdx * 32 + lane];

        // ---- erode vertical (in registers) ----
        float4 en[4];
        en[0] = vmin3(up, rm[0], rm[1]);
        en[1] = vmin3(rm[0], rm[1], rm[2]);
        en[2] = vmin3(rm[1], rm[2], rm[3]);
        en[3] = vmin3(rm[2], rm[3], dn);

        // force image-OOB cells back to pad (-1); border blocks only
        if (bord) {
            const bool c0 = (unsigned)(gx0 + 0) < W;
            const bool c1 = (unsigned)(gx0 + 1) < W;
            const bool c2 = (unsigned)(gx0 + 2) < W;
            const bool c3 = (unsigned)(gx0 + 3) < W;
            #pragma unroll
            for (int i = 0; i < 4; i++) {
                const bool r = (unsigned)(gy0 + i) < H;
                en[i].x = (r & c0) ? en[i].x : -1.f;
                en[i].y = (r & c1) ? en[i].y : -1.f;
                en[i].z = (r & c2) ? en[i].z : -1.f;
                en[i].w = (r & c3) ? en[i].w : -1.f;
            }
        }

        // ---- dilate horizontal + exchange (only warps near center) ----
        float4 xm[4];
        if (dilateW) {
            #pragma unroll
            for (int i = 0; i < 4; i++) xm[i] = hmax_(en[i]);
            exB[(wid * 2 + 0) * 32 + lane] = xm[0];
            exB[(wid * 2 + 1) * 32 + lane] = xm[3];
        }
        __syncthreads();

        // ---- dilate vertical -> open; delta; skel recurrence (center only) ----
        if (centerW) {
            float4 u = exB[((wid - 1) * 2 + 1) * 32 + lane];
            float4 d = exB[((wid + 1) * 2 + 0) * 32 + lane];
            float4 op0 = vmax3(u,     xm[0], xm[1]);
            float4 op1 = vmax3(xm[0], xm[1], xm[2]);
            float4 op2 = vmax3(xm[1], xm[2], xm[3]);
            float4 op3 = vmax3(xm[2], xm[3], d);
            // delta = e - open (>= 0 exactly: opening is anti-extensive)
            // skel' = skel + delta - skel*delta   (relu provably no-op, tol 1e-3)
            float4 dl;
            dl.x = e[0].x - op0.x; dl.y = e[0].y - op0.y; dl.z = e[0].z - op0.z; dl.w = e[0].w - op0.w;
            sk[0].x = fmaf(-sk[0].x, dl.x, sk[0].x + dl.x);
            sk[0].y = fmaf(-sk[0].y, dl.y, sk[0].y + dl.y);
            sk[0].z = fmaf(-sk[0].z, dl.z, sk[0].z + dl.z);
            sk[0].w = fmaf(-sk[0].w, dl.w, sk[0].w + dl.w);
            dl.x = e[1].x - op1.x; dl.y = e[1].y - op1.y; dl.z = e[1].z - op1.z; dl.w = e[1].w - op1.w;
            sk[1].x = fmaf(-sk[1].x, dl.x, sk[1].x + dl.x);
            sk[1].y = fmaf(-sk[1].y, dl.y, sk[1].y + dl.y);
            sk[1].z = fmaf(-sk[1].z, dl.z, sk[1].z + dl.z);
            sk[1].w = fmaf(-sk[1].w, dl.w, sk[1].w + dl.w);
            dl.x = e[2].x - op2.x; dl.y = e[2].y - op2.y; dl.z = e[2].z - op2.z; dl.w = e[2].w - op2.w;
            sk[2].x = fmaf(-sk[2].x, dl.x, sk[2].x + dl.x);
            sk[2].y = fmaf(-sk[2].y, dl.y, sk[2].y + dl.y);
            sk[2].z = fmaf(-sk[2].z, dl.z, sk[2].z + dl.z);
            sk[2].w = fmaf(-sk[2].w, dl.w, sk[2].w + dl.w);
            dl.x = e[3].x - op3.x; dl.y = e[3].y - op3.y; dl.z = e[3].z - op3.z; dl.w = e[3].w - op3.w;
            sk[3].x = fmaf(-sk[3].x, dl.x, sk[3].x + dl.x);
            sk[3].y = fmaf(-sk[3].y, dl.y, sk[3].y + dl.y);
            sk[3].z = fmaf(-sk[3].z, dl.z, sk[3].z + dl.z);
            sk[3].w = fmaf(-sk[3].w, dl.w, sk[3].w + dl.w);
        }
        #pragma unroll
        for (int i = 0; i < 4; i++) e[i] = en[i];
    }

    // ---- partial sums over this thread's 4 center rows ----
    float sa = 0.f, sb = 0.f;
    if (centerW) {
        const float* oimg = isPred ? tgt  + (size_t)b * H * W
                                   : pred + (size_t)(b - 8) * H * W;
        const bool oSig = !isPred;
        const bool c0 = (unsigned)(gx0 + 0) < W;
        const bool c3 = (unsigned)(gx0 + 3) < W;
        #pragma unroll
        for (int i = 0; i < 4; i++) {
            const int gy = gy0 + i;
            if ((unsigned)gy < H) {
                const float* row = oimg + (size_t)gy * W;
                if (c0 & c3) {
                    float4 w = *reinterpret_cast<const float4*>(row + gx0);
                    if (oSig) { w.x = sig_(w.x); w.y = sig_(w.y); w.z = sig_(w.z); w.w = sig_(w.w); }
                    sa += sk[i].x * w.x + sk[i].y * w.y + sk[i].z * w.z + sk[i].w * w.w;
                    sb += sk[i].x + sk[i].y + sk[i].z + sk[i].w;
                } else {
                    float s[4] = { sk[i].x, sk[i].y, sk[i].z, sk[i].w };
                    #pragma unroll
                    for (int j = 0; j < 4; j++) {
                        if ((unsigned)(gx0 + j) < W) {
                            float w = row[gx0 + j];
                            if (oSig) w = sig_(w);
                            sa += s[j] * w;
                            sb += s[j];
                        }
                    }
                }
            }
        }
    }

    // ---- block reduction (reuse exA; all prior exA reads complete) ----
    #pragma unroll
    for (int o = 16; o; o >>= 1) {
        sa += __shfl_down_sync(0xffffffffu, sa, o);
        sb += __shfl_down_sync(0xffffffffu, sb, o);
    }
    float2* sred = (float2*)exA;
    if (lane == 0) sred[wid] = make_float2(sa, sb);
    __syncthreads();
    if (wid == 0) {
        float2 p = sred[lane];
        float a = p.x, c = p.y;
        #pragma unroll
        for (int o = 16; o; o >>= 1) {
            a += __shfl_down_sync(0xffffffffu, a, o);
            c += __shfl_down_sync(0xffffffffu, c, o);
        }
        if (lane == 0) {
            atomicAdd(&g_sums[isPred ? 0 : 2], a);
            atomicAdd(&g_sums[isPred ? 1 : 3], c);
        }
    }
}

__global__ void final_kernel(float* __restrict__ out) {
    float S1 = g_sums[0], S2 = g_sums[1], S3 = g_sums[2], S4 = g_sums[3];
    float tp = (S1 + 1.0f) / (S2 + 1.0f);
    float ts = (S3 + 1.0f) / (S4 + 1.0f);
    float cl = 2.0f * tp * ts / (tp + ts + 1e-7f);
    out[0] = 1.0f - cl;
    // self-clean for the next graph replay
    g_sums[0] = 0.f; g_sums[1] = 0.f; g_sums[2] = 0.f; g_sums[3] = 0.f;
}

extern "C" void kernel_launch(void* const* d_in, const int* in_sizes, int n_in,
                              void* d_out, int out_size)
{
    const float* pred = (const float*)d_in[0];
    const float* tgt  = (const float*)d_in[1];
    float* out = (float*)d_out;

    size_t shmem = (size_t)4096 * sizeof(float4);  // exA(32KB) + exB(32KB)
    cudaFuncSetAttribute(cl_main, cudaFuncAttributeMaxDynamicSharedMemorySize, (int)shmem);

    cl_main<<<dim3(G, G, NB), 1024, shmem>>>(pred, tgt);
    final_kernel<<<1, 1>>>(out);

    (void)in_sizes; (void)n_in; (void)out_size;
}

// round 5
// speedup vs baseline: 9.1788x; 1.1562x over previous
#include <cuda_runtime.h>
#include <cuda_fp16.h>
#include <cstdint>

#define H 1024
#define W 1024
#define TS 104          // square output tile (floats)
#define G  10           // 10*104 = 1040 >= 1024 (both dims)
#define NB 16           // 8 pred + 8 target

__device__ float g_sums[4];

__device__ __forceinline__ float sig_(float x) { return 1.0f / (1.0f + __expf(-x)); }

__device__ __forceinline__ float4 vmin2(float4 a, float4 b) {
    return make_float4(fminf(a.x,b.x), fminf(a.y,b.y), fminf(a.z,b.z), fminf(a.w,b.w));
}
__device__ __forceinline__ float4 vmax2(float4 a, float4 b) {
    return make_float4(fmaxf(a.x,b.x), fmaxf(a.y,b.y), fmaxf(a.z,b.z), fmaxf(a.w,b.w));
}

// horizontal 3-min with |.| pad-remap (pads stored as -1; |-1|=1 >= all data in [0,1))
__device__ __forceinline__ float4 hmin_abs(float4 v) {
    float lw = __shfl_up_sync(0xffffffffu, v.w, 1);
    float rx = __shfl_down_sync(0xffffffffu, v.x, 1);
    float ax = fabsf(v.x), ay = fabsf(v.y), az = fabsf(v.z), aw = fabsf(v.w);
    float t1 = fminf(ax, ay), t2 = fminf(ay, az), t3 = fminf(az, aw);
    float4 o;
    o.x = fminf(fabsf(lw), t1);
    o.y = fminf(t1, az);
    o.z = fminf(t2, aw);
    o.w = fminf(t3, fabsf(rx));
    return o;
}

__device__ __forceinline__ float4 hmax_(float4 v) {
    float lw = __shfl_up_sync(0xffffffffu, v.w, 1);
    float rx = __shfl_down_sync(0xffffffffu, v.x, 1);
    float t1 = fmaxf(v.x, v.y), t2 = fmaxf(v.y, v.z), t3 = fmaxf(v.z, v.w);
    float4 o;
    o.x = fmaxf(lw, t1);
    o.y = fmaxf(t1, v.z);
    o.z = fmaxf(t2, v.w);
    o.w = fmaxf(t3, rx);
    return o;
}

__device__ __forceinline__ float4 load_row(const float* __restrict__ img, int gy, int gx0, bool doSig)
{
    float4 v;
    if ((unsigned)gy < H) {
        const float* row = img + (size_t)gy * W;
        if (gx0 >= 0 && gx0 + 3 < W) {
            v = *reinterpret_cast<const float4*>(row + gx0);
            if (doSig) { v.x = sig_(v.x); v.y = sig_(v.y); v.z = sig_(v.z); v.w = sig_(v.w); }
        } else {
            v.x = ((unsigned)(gx0+0) < W) ? (doSig ? sig_(row[gx0+0]) : row[gx0+0]) : -1.0f;
            v.y = ((unsigned)(gx0+1) < W) ? (doSig ? sig_(row[gx0+1]) : row[gx0+1]) : -1.0f;
            v.z = ((unsigned)(gx0+2) < W) ? (doSig ? sig_(row[gx0+2]) : row[gx0+2]) : -1.0f;
            v.w = ((unsigned)(gx0+3) < W) ? (doSig ? sig_(row[gx0+3]) : row[gx0+3]) : -1.0f;
        }
    } else {
        v = make_float4(-1.f, -1.f, -1.f, -1.f);
    }
    return v;
}

// buffer: 128 rows x 128 cols; warp w owns rows 4w..4w+3; lane = f4 column.
__global__ __launch_bounds__(1024, 1)
void cl_main(const float* __restrict__ pred, const float* __restrict__ tgt)
{
    extern __shared__ float4 smem_[];
    float4* exA = smem_;           // [wid*2 + s][lane] : erode rowmin boundary rows
    float4* exB = smem_ + 2048;    // [wid*2 + s][lane] : dilate rowmax boundary rows

    const int tid  = threadIdx.x;
    const int lane = tid & 31;
    const int wid  = tid >> 5;
    const int bx = blockIdx.x, by = blockIdx.y, b = blockIdx.z;
    const bool isPred = (b < 8);
    const float* img = isPred ? pred + (size_t)b * H * W
                              : tgt  + (size_t)(b - 8) * H * W;

    const int gx0 = bx * TS - 12 + 4 * lane;     // global col of component .x
    const int gy0 = by * TS - 12 + 4 * wid;      // global row of this thread's row 0

    // per-thread OOB flag: any of this thread's 16 cells outside the image
    const bool thrOOB = ((unsigned)gy0 > (unsigned)(H - 4)) ||
                        ((unsigned)gx0 > (unsigned)(W - 4));

    // ---- load e (4 rows), pads = -1 ----
    float4 e[4];
    #pragma unroll
    for (int i = 0; i < 4; i++) e[i] = load_row(img, gy0 + i, gx0, isPred);

    __half2 skh[4];  // per row: (px0,px1) ... only 2 of 4 px? -> use 2 half2 per row? No:
    // we need 4 px per row -> 2 half2 per row = 8 regs total for 4 rows.
    __half2 skl[4];  // low pair (x,y) per row
    #pragma unroll
    for (int i = 0; i < 4; i++) {
        skl[i] = __float2half2_rn(0.f);
        skh[i] = __float2half2_rn(0.f);
    }

    const int upIdx = (wid == 0)  ? 1       : (wid - 1) * 2 + 1;
    const int dnIdx = (wid == 31) ? wid * 2 : (wid + 1) * 2;
    const bool dilateW = (wid >= 2) && (wid <= 29);
    const bool centerW = (wid >= 3) && (wid <= 28) && (lane >= 3) && (lane <= 28);

    const __half2 h2zero = __float2half2_rn(0.f);

    #pragma unroll
    for (int k = 0; k < 11; k++) {
        // ---- erode horizontal (regs + shuffle) ----
        float4 rm0 = hmin_abs(e[0]);
        float4 rm1 = hmin_abs(e[1]);
        float4 rm2 = hmin_abs(e[2]);
        float4 rm3 = hmin_abs(e[3]);

        exA[(wid * 2 + 0) * 32 + lane] = rm0;
        exA[(wid * 2 + 1) * 32 + lane] = rm3;
        __syncthreads();
        float4 up = exA[upIdx * 32 + lane];
        float4 dn = exA[dnIdx * 32 + lane];

        // ---- erode vertical (registers, CSE) ----
        float4 m01 = vmin2(rm0, rm1);
        float4 m23 = vmin2(rm2, rm3);
        float4 en0 = vmin2(up,  m01);
        float4 en1 = vmin2(m01, rm2);
        float4 en2 = vmin2(rm1, m23);
        float4 en3 = vmin2(m23, dn);

        // force image-OOB cells back to pad (-1); only threads that own OOB cells
        if (thrOOB) {
            const bool c0 = (unsigned)(gx0 + 0) < W;
            const bool c1 = (unsigned)(gx0 + 1) < W;
            const bool c2 = (unsigned)(gx0 + 2) < W;
            const bool c3 = (unsigned)(gx0 + 3) < W;
            float4* enp[4] = { &en0, &en1, &en2, &en3 };
            #pragma unroll
            for (int i = 0; i < 4; i++) {
                const bool r = (unsigned)(gy0 + i) < H;
                enp[i]->x = (r & c0) ? enp[i]->x : -1.f;
                enp[i]->y = (r & c1) ? enp[i]->y : -1.f;
                enp[i]->z = (r & c2) ? enp[i]->z : -1.f;
                enp[i]->w = (r & c3) ? enp[i]->w : -1.f;
            }
        }

        // ---- dilate horizontal + exchange (only warps near center) ----
        float4 xm0, xm1, xm2, xm3;
        if (dilateW) {
            xm0 = hmax_(en0);
            xm1 = hmax_(en1);
            xm2 = hmax_(en2);
            xm3 = hmax_(en3);
            exB[(wid * 2 + 0) * 32 + lane] = xm0;
            exB[(wid * 2 + 1) * 32 + lane] = xm3;
        }
        __syncthreads();

        // ---- dilate vertical -> open; delta; skel recurrence (center only) ----
        if (centerW) {
            float4 u = exB[((wid - 1) * 2 + 1) * 32 + lane];
            float4 d = exB[((wid + 1) * 2 + 0) * 32 + lane];
            float4 x01 = vmax2(xm0, xm1);
            float4 x23 = vmax2(xm2, xm3);
            float4 op0 = vmax2(u,   x01);
            float4 op1 = vmax2(x01, xm2);
            float4 op2 = vmax2(xm1, x23);
            float4 op3 = vmax2(x23, d);

            float4 ee, oo;
            // row 0
            ee = e[0]; oo = op0;
            {
                __half2 dlo = __floats2half2_rn(ee.x - oo.x, ee.y - oo.y);
                __half2 dhi = __floats2half2_rn(ee.z - oo.z, ee.w - oo.w);
                __half2 t;
                t = __hmax2(__hfma2(skl[0], __hneg2(dlo), dlo), h2zero);
                skl[0] = __hadd2(skl[0], t);
                t = __hmax2(__hfma2(skh[0], __hneg2(dhi), dhi), h2zero);
                skh[0] = __hadd2(skh[0], t);
            }
            // row 1
            ee = e[1]; oo = op1;
            {
                __half2 dlo = __floats2half2_rn(ee.x - oo.x, ee.y - oo.y);
                __half2 dhi = __floats2half2_rn(ee.z - oo.z, ee.w - oo.w);
                __half2 t;
                t = __hmax2(__hfma2(skl[1], __hneg2(dlo), dlo), h2zero);
                skl[1] = __hadd2(skl[1], t);
                t = __hmax2(__hfma2(skh[1], __hneg2(dhi), dhi), h2zero);
                skh[1] = __hadd2(skh[1], t);
            }
            // row 2
            ee = e[2]; oo = op2;
            {
                __half2 dlo = __floats2half2_rn(ee.x - oo.x, ee.y - oo.y);
                __half2 dhi = __floats2half2_rn(ee.z - oo.z, ee.w - oo.w);
                __half2 t;
                t = __hmax2(__hfma2(skl[2], __hneg2(dlo), dlo), h2zero);
                skl[2] = __hadd2(skl[2], t);
                t = __hmax2(__hfma2(skh[2], __hneg2(dhi), dhi), h2zero);
                skh[2] = __hadd2(skh[2], t);
            }
            // row 3
            ee = e[3]; oo = op3;
            {
                __half2 dlo = __floats2half2_rn(ee.x - oo.x, ee.y - oo.y);
                __half2 dhi = __floats2half2_rn(ee.z - oo.z, ee.w - oo.w);
                __half2 t;
                t = __hmax2(__hfma2(skl[3], __hneg2(dlo), dlo), h2zero);
                skl[3] = __hadd2(skl[3], t);
                t = __hmax2(__hfma2(skh[3], __hneg2(dhi), dhi), h2zero);
                skh[3] = __hadd2(skh[3], t);
            }
        }
        e[0] = en0; e[1] = en1; e[2] = en2; e[3] = en3;
    }

    // ---- partial sums over this thread's 4 center rows ----
    float sa = 0.f, sb = 0.f;
    if (centerW) {
        const float* oimg = isPred ? tgt  + (size_t)b * H * W
                                   : pred + (size_t)(b - 8) * H * W;
        const bool oSig = !isPred;
        const bool c0 = (unsigned)(gx0 + 0) < W;
        const bool c3 = (unsigned)(gx0 + 3) < W;
        #pragma unroll
        for (int i = 0; i < 4; i++) {
            const int gy = gy0 + i;
            if ((unsigned)gy < H) {
                float2 lo = __half22float2(skl[i]);
                float2 hi = __half22float2(skh[i]);
                float s0 = lo.x, s1 = lo.y, s2 = hi.x, s3 = hi.y;
                const float* row = oimg + (size_t)gy * W;
                if (c0 & c3) {
                    float4 w = *reinterpret_cast<const float4*>(row + gx0);
                    if (oSig) { w.x = sig_(w.x); w.y = sig_(w.y); w.z = sig_(w.z); w.w = sig_(w.w); }
                    sa += s0 * w.x + s1 * w.y + s2 * w.z + s3 * w.w;
                    sb += s0 + s1 + s2 + s3;
                } else {
                    float s[4] = { s0, s1, s2, s3 };
                    #pragma unroll
                    for (int j = 0; j < 4; j++) {
                        if ((unsigned)(gx0 + j) < W) {
                            float w = row[gx0 + j];
                            if (oSig) w = sig_(w);
                            sa += s[j] * w;
                            sb += s[j];
                        }
                    }
                }
            }
        }
    }

    // ---- block reduction (reuse exA) ----
    #pragma unroll
    for (int o = 16; o; o >>= 1) {
        sa += __shfl_down_sync(0xffffffffu, sa, o);
        sb += __shfl_down_sync(0xffffffffu, sb, o);
    }
    float2* sred = (float2*)exA;
    if (lane == 0) sred[wid] = make_float2(sa, sb);
    __syncthreads();
    if (wid == 0) {
        float2 p = sred[lane];
        float a = p.x, c = p.y;
        #pragma unroll
        for (int o = 16; o; o >>= 1) {
            a += __shfl_down_sync(0xffffffffu, a, o);
            c += __shfl_down_sync(0xffffffffu, c, o);
        }
        if (lane == 0) {
            atomicAdd(&g_sums[isPred ? 0 : 2], a);
            atomicAdd(&g_sums[isPred ? 1 : 3], c);
        }
    }
}

__global__ void final_kernel(float* __restrict__ out) {
    float S1 = g_sums[0], S2 = g_sums[1], S3 = g_sums[2], S4 = g_sums[3];
    float tp = (S1 + 1.0f) / (S2 + 1.0f);
    float ts = (S3 + 1.0f) / (S4 + 1.0f);
    float cl = 2.0f * tp * ts / (tp + ts + 1e-7f);
    out[0] = 1.0f - cl;
    // self-clean for the next graph replay
    g_sums[0] = 0.f; g_sums[1] = 0.f; g_sums[2] = 0.f; g_sums[3] = 0.f;
}

extern "C" void kernel_launch(void* const* d_in, const int* in_sizes, int n_in,
                              void* d_out, int out_size)
{
    const float* pred = (const float*)d_in[0];
    const float* tgt  = (const float*)d_in[1];
    float* out = (float*)d_out;

    size_t shmem = (size_t)4096 * sizeof(float4);  // exA(32KB) + exB(32KB)
    cudaFuncSetAttribute(cl_main, cudaFuncAttributeMaxDynamicSharedMemorySize, (int)shmem);

    cl_main<<<dim3(G, G, NB), 1024, shmem>>>(pred, tgt);
    final_kernel<<<1, 1>>>(out);

    (void)in_sizes; (void)n_in; (void)out_size;
}

// round 6
// speedup vs baseline: 14.4935x; 1.5790x over previous
#include <cuda_runtime.h>
#include <cuda_fp16.h>
#include <cstdint>

#define H 1024
#define W 1024
#define TS 104          // square output tile (floats/pixels)
#define G  10           // 10*104 = 1040 >= 1024 (both dims)
#define NB 16           // 8 pred + 8 target

typedef unsigned int u32;

__device__ float g_sums[4];

__device__ __forceinline__ float sig_(float x) { return 1.0f / (1.0f + __expf(-x)); }

__device__ __forceinline__ u32 h2u(__half2 h) { return *reinterpret_cast<u32*>(&h); }
__device__ __forceinline__ __half2 u2h(u32 u) { return *reinterpret_cast<__half2*>(&u); }

// load 4 fp32 px, pad image-OOB with +1.0 (acts as +inf for erode over data < 1)
__device__ __forceinline__ float4 load_row(const float* __restrict__ img, int gy, int gx0, bool doSig)
{
    float4 v;
    if ((unsigned)gy < H) {
        const float* row = img + (size_t)gy * W;
        if (gx0 >= 0 && gx0 + 3 < W) {
            v = *reinterpret_cast<const float4*>(row + gx0);
            if (doSig) { v.x = sig_(v.x); v.y = sig_(v.y); v.z = sig_(v.z); v.w = sig_(v.w); }
        } else {
            v.x = ((unsigned)(gx0+0) < W) ? (doSig ? sig_(row[gx0+0]) : row[gx0+0]) : 1.0f;
            v.y = ((unsigned)(gx0+1) < W) ? (doSig ? sig_(row[gx0+1]) : row[gx0+1]) : 1.0f;
            v.z = ((unsigned)(gx0+2) < W) ? (doSig ? sig_(row[gx0+2]) : row[gx0+2]) : 1.0f;
            v.w = ((unsigned)(gx0+3) < W) ? (doSig ? sig_(row[gx0+3]) : row[gx0+3]) : 1.0f;
        }
    } else {
        v = make_float4(1.f, 1.f, 1.f, 1.f);
    }
    return v;
}

// buffer: 128 rows x 128 cols (fp16); warp w owns rows 4w..4w+3; lane = 4-px column group.
__global__ __launch_bounds__(1024, 1)
void cl_main(const float* __restrict__ pred, const float* __restrict__ tgt)
{
    extern __shared__ uint2 smem_[];
    uint2* exA = smem_;           // [64][32] erode rowmin boundary rows
    uint2* exB = smem_ + 2048;    // [64][32] dilate rowmax boundary rows

    const int tid  = threadIdx.x;
    const int lane = tid & 31;
    const int wid  = tid >> 5;
    const int bx = blockIdx.x, by = blockIdx.y, b = blockIdx.z;
    const bool isPred = (b < 8);
    const float* img = isPred ? pred + (size_t)b * H * W
                              : tgt  + (size_t)(b - 8) * H * W;

    const int gx0 = bx * TS - 12 + 4 * lane;
    const int gy0 = by * TS - 12 + 4 * wid;
    const bool thrOOB = ((unsigned)gy0 > (unsigned)(H - 4)) ||
                        ((unsigned)gx0 > (unsigned)(W - 4));

    // keep-masks per half2 (0xFFFF per in-image px)
    u32 kma[4], kmb[4];
    {
        const u32 ca = (((unsigned)(gx0+0) < W) ? 0x0000FFFFu : 0u)
                     | (((unsigned)(gx0+1) < W) ? 0xFFFF0000u : 0u);
        const u32 cb = (((unsigned)(gx0+2) < W) ? 0x0000FFFFu : 0u)
                     | (((unsigned)(gx0+3) < W) ? 0xFFFF0000u : 0u);
        #pragma unroll
        for (int i = 0; i < 4; i++) {
            const bool rv = (unsigned)(gy0 + i) < H;
            kma[i] = rv ? ca : 0u;
            kmb[i] = rv ? cb : 0u;
        }
    }
    const u32 PADHI = 0x3C003C00u;  // (+1,+1) fp16
    const u32 PADLO = 0xBC00BC00u;  // (-1,-1) fp16

    // ---- load e (4 rows x 4 px -> 2 half2/row) ----
    __half2 ea[4], eb[4];
    #pragma unroll
    for (int i = 0; i < 4; i++) {
        float4 v = load_row(img, gy0 + i, gx0, isPred);
        ea[i] = __floats2half2_rn(v.x, v.y);
        eb[i] = __floats2half2_rn(v.z, v.w);
    }

    __half2 ska[4], skb[4];
    const __half2 h2z = __float2half2_rn(0.f);
    #pragma unroll
    for (int i = 0; i < 4; i++) { ska[i] = h2z; skb[i] = h2z; }

    const int upIdx = (wid == 0)  ? 1       : (wid - 1) * 2 + 1;
    const int dnIdx = (wid == 31) ? wid * 2 : (wid + 1) * 2;
    const bool dilateW = (wid >= 2) && (wid <= 29);
    const bool centerW = (wid >= 3) && (wid <= 28) && (lane >= 3) && (lane <= 28);

    #pragma unroll
    for (int k = 0; k < 11; k++) {
        // ---- erode horizontal: shuffles + PRMT shifts + HMNMX2 ----
        __half2 rma[4], rmb[4];
        #pragma unroll
        for (int i = 0; i < 4; i++) {
            u32 ua = h2u(ea[i]), ub = h2u(eb[i]);
            u32 lw = __shfl_up_sync(0xffffffffu, ub, 1);
            u32 rx = __shfl_down_sync(0xffffffffu, ua, 1);
            u32 la = __byte_perm(lw, ua, 0x5432);   // (p-1,p0)
            u32 mi = __byte_perm(ua, ub, 0x5432);   // (p1,p2)
            u32 rb = __byte_perm(ub, rx, 0x5432);   // (p3,p4)
            rma[i] = __hmin2(__hmin2(u2h(la), ea[i]), u2h(mi));
            rmb[i] = __hmin2(__hmin2(u2h(mi), eb[i]), u2h(rb));
        }
        exA[(wid * 2 + 0) * 32 + lane] = make_uint2(h2u(rma[0]), h2u(rmb[0]));
        exA[(wid * 2 + 1) * 32 + lane] = make_uint2(h2u(rma[3]), h2u(rmb[3]));
        __syncthreads();
        const uint2 upu = exA[upIdx * 32 + lane];
        const uint2 dnu = exA[dnIdx * 32 + lane];

        // ---- erode vertical (registers, CSE) ----
        __half2 m01a = __hmin2(rma[0], rma[1]), m23a = __hmin2(rma[2], rma[3]);
        __half2 m01b = __hmin2(rmb[0], rmb[1]), m23b = __hmin2(rmb[2], rmb[3]);
        __half2 ena[4], enb[4];
        ena[0] = __hmin2(u2h(upu.x), m01a);
        ena[1] = __hmin2(m01a, rma[2]);
        ena[2] = __hmin2(rma[1], m23a);
        ena[3] = __hmin2(m23a, u2h(dnu.x));
        enb[0] = __hmin2(u2h(upu.y), m01b);
        enb[1] = __hmin2(m01b, rmb[2]);
        enb[2] = __hmin2(rmb[1], m23b);
        enb[3] = __hmin2(m23b, u2h(dnu.y));

        // ---- forcing: dilate-input pad=-1, next-e pad=+1 (border threads only) ----
        __half2 eda[4], edb[4];
        if (thrOOB) {
            #pragma unroll
            for (int i = 0; i < 4; i++) {
                u32 xa = h2u(ena[i]), xb = h2u(enb[i]);
                eda[i] = u2h((xa & kma[i]) | (PADLO & ~kma[i]));
                edb[i] = u2h((xb & kmb[i]) | (PADLO & ~kmb[i]));
                ena[i] = u2h((xa & kma[i]) | (PADHI & ~kma[i]));
                enb[i] = u2h((xb & kmb[i]) | (PADHI & ~kmb[i]));
            }
        } else {
            #pragma unroll
            for (int i = 0; i < 4; i++) { eda[i] = ena[i]; edb[i] = enb[i]; }
        }

        // ---- dilate horizontal + exchange (warps near center) ----
        __half2 xma[4], xmb[4];
        if (dilateW) {
            #pragma unroll
            for (int i = 0; i < 4; i++) {
                u32 ua = h2u(eda[i]), ub = h2u(edb[i]);
                u32 lw = __shfl_up_sync(0xffffffffu, ub, 1);
                u32 rx = __shfl_down_sync(0xffffffffu, ua, 1);
                u32 la = __byte_perm(lw, ua, 0x5432);
                u32 mi = __byte_perm(ua, ub, 0x5432);
                u32 rb = __byte_perm(ub, rx, 0x5432);
                xma[i] = __hmax2(__hmax2(u2h(la), eda[i]), u2h(mi));
                xmb[i] = __hmax2(__hmax2(u2h(mi), edb[i]), u2h(rb));
            }
            exB[(wid * 2 + 0) * 32 + lane] = make_uint2(h2u(xma[0]), h2u(xmb[0]));
            exB[(wid * 2 + 1) * 32 + lane] = make_uint2(h2u(xma[3]), h2u(xmb[3]));
        }
        __syncthreads();

        // ---- dilate vertical -> open; delta; skel recurrence (center only) ----
        if (centerW) {
            const uint2 uu = exB[((wid - 1) * 2 + 1) * 32 + lane];
            const uint2 dd = exB[((wid + 1) * 2 + 0) * 32 + lane];
            __half2 x01a = __hmax2(xma[0], xma[1]), x23a = __hmax2(xma[2], xma[3]);
            __half2 x01b = __hmax2(xmb[0], xmb[1]), x23b = __hmax2(xmb[2], xmb[3]);
            __half2 opa[4], opb[4];
            opa[0] = __hmax2(u2h(uu.x), x01a);
            opa[1] = __hmax2(x01a, xma[2]);
            opa[2] = __hmax2(xma[1], x23a);
            opa[3] = __hmax2(x23a, u2h(dd.x));
            opb[0] = __hmax2(u2h(uu.y), x01b);
            opb[1] = __hmax2(x01b, xmb[2]);
            opb[2] = __hmax2(xmb[1], x23b);
            opb[3] = __hmax2(x23b, u2h(dd.y));
            #pragma unroll
            for (int i = 0; i < 4; i++) {
                __half2 d, t;
                d = __hsub2(ea[i], opa[i]);
                t = __hmax2(__hfma2(ska[i], __hneg2(d), d), h2z);
                ska[i] = __hadd2(ska[i], t);
                d = __hsub2(eb[i], opb[i]);
                t = __hmax2(__hfma2(skb[i], __hneg2(d), d), h2z);
                skb[i] = __hadd2(skb[i], t);
            }
        }
        #pragma unroll
        for (int i = 0; i < 4; i++) { ea[i] = ena[i]; eb[i] = enb[i]; }
    }

    // ---- partial sums over this thread's 4 center rows ----
    float sa = 0.f, sb = 0.f;
    if (centerW) {
        const float* oimg = isPred ? tgt  + (size_t)b * H * W
                                   : pred + (size_t)(b - 8) * H * W;
        const bool oSig = !isPred;
        const bool c0 = (unsigned)(gx0 + 0) < W;
        const bool c3 = (unsigned)(gx0 + 3) < W;
        #pragma unroll
        for (int i = 0; i < 4; i++) {
            const int gy = gy0 + i;
            if ((unsigned)gy < H) {
                float2 lo = __half22float2(ska[i]);
                float2 hi = __half22float2(skb[i]);
                const float* row = oimg + (size_t)gy * W;
                if (c0 & c3) {
                    float4 w = *reinterpret_cast<const float4*>(row + gx0);
                    if (oSig) { w.x = sig_(w.x); w.y = sig_(w.y); w.z = sig_(w.z); w.w = sig_(w.w); }
                    sa += lo.x * w.x + lo.y * w.y + hi.x * w.z + hi.y * w.w;
                    sb += lo.x + lo.y + hi.x + hi.y;
                } else {
                    float s[4] = { lo.x, lo.y, hi.x, hi.y };
                    #pragma unroll
                    for (int j = 0; j < 4; j++) {
                        if ((unsigned)(gx0 + j) < W) {
                            float w = row[gx0 + j];
                            if (oSig) w = sig_(w);
                            sa += s[j] * w;
                            sb += s[j];
                        }
                    }
                }
            }
        }
    }

    // ---- block reduction (reuse exA) ----
    #pragma unroll
    for (int o = 16; o; o >>= 1) {
        sa += __shfl_down_sync(0xffffffffu, sa, o);
        sb += __shfl_down_sync(0xffffffffu, sb, o);
    }
    float2* sred = (float2*)exA;
    if (lane == 0) sred[wid] = make_float2(sa, sb);
    __syncthreads();
    if (wid == 0) {
        float2 p = sred[lane];
        float a = p.x, c = p.y;
        #pragma unroll
        for (int o = 16; o; o >>= 1) {
            a += __shfl_down_sync(0xffffffffu, a, o);
            c += __shfl_down_sync(0xffffffffu, c, o);
        }
        if (lane == 0) {
            atomicAdd(&g_sums[isPred ? 0 : 2], a);
            atomicAdd(&g_sums[isPred ? 1 : 3], c);
        }
    }
}

__global__ void final_kernel(float* __restrict__ out) {
    float S1 = g_sums[0], S2 = g_sums[1], S3 = g_sums[2], S4 = g_sums[3];
    float tp = (S1 + 1.0f) / (S2 + 1.0f);
    float ts = (S3 + 1.0f) / (S4 + 1.0f);
    float cl = 2.0f * tp * ts / (tp + ts + 1e-7f);
    out[0] = 1.0f - cl;
    g_sums[0] = 0.f; g_sums[1] = 0.f; g_sums[2] = 0.f; g_sums[3] = 0.f;
}

extern "C" void kernel_launch(void* const* d_in, const int* in_sizes, int n_in,
                              void* d_out, int out_size)
{
    const float* pred = (const float*)d_in[0];
    const float* tgt  = (const float*)d_in[1];
    float* out = (float*)d_out;

    size_t shmem = (size_t)4096 * sizeof(uint2);  // exA(16KB)+exB(16KB)
    cudaFuncSetAttribute(cl_main, cudaFuncAttributeMaxDynamicSharedMemorySize, (int)shmem);

    cl_main<<<dim3(G, G, NB), 1024, shmem>>>(pred, tgt);
    final_kernel<<<1, 1>>>(out);

    (void)in_sizes; (void)n_in; (void)out_size;
}